// round 2
// baseline (speedup 1.0000x reference)
#include <cuda_runtime.h>
#include <math.h>
#include <stdint.h>

// Problem constants
#define T_STEPS 512
#define NBATCH  1024
#define IDIM    64
#define RDIM    256
#define NCTA    128
#define NTHR    256
#define BM      64   // batch rows per CTA
#define BN      32   // output cols per CTA

// -------- global scratch (no cudaMalloc allowed) --------
__device__ float g_h[NBATCH * RDIM];       // hidden state [1024][256]
__device__ float g_cat[NBATCH * 2 * RDIM]; // concat buffer [1024][512]
__device__ float g_m[NBATCH * RDIM];       // meshup output [1024][256]
__device__ float g_r1p[8 * NBATCH];        // regressor partials per col-tile
__device__ unsigned g_bar_count = 0;
__device__ unsigned g_bar_gen = 0;

// -------- grid-wide sense-reversing barrier --------
__device__ __forceinline__ void grid_barrier() {
    __threadfence();
    __syncthreads();
    if (threadIdx.x == 0) {
        unsigned g = *((volatile unsigned*)&g_bar_gen);
        unsigned old = atomicAdd(&g_bar_count, 1u);
        if (old == NCTA - 1) {
            g_bar_count = 0;
            __threadfence();
            *((volatile unsigned*)&g_bar_gen) = g + 1;
        } else {
            while (*((volatile unsigned*)&g_bar_gen) == g) { }
        }
    }
    __syncthreads();
}

// -------- tiled GEMM: C[64 x 32] (+opt second C) = A[64 x K] @ Wsmem[K x 32] --------
// A streamed from global (L2) in 64x64 chunks through smem staging.
// Thread layout: c = tid & 31 (output col), rbase = (tid>>5)*8 (8 output rows).
template <int K, bool FUSE2>
__device__ __forceinline__ void gemm64(
    const float* __restrict__ Aglob, int lda, int row0,
    const float* __restrict__ Ws1, const float* __restrict__ Ws2,
    float* As, float acc1[8], float acc2[8], int c, int rbase)
{
    for (int k0 = 0; k0 < K; k0 += 64) {
        __syncthreads();
        // stage 64x64 chunk: 1024 float4 loads across 256 threads
        #pragma unroll
        for (int i = threadIdx.x; i < 1024; i += NTHR) {
            int r = i >> 4;
            int kk = (i & 15) << 2;
            float4 v = __ldcg((const float4*)(Aglob + (size_t)(row0 + r) * lda + k0 + kk));
            *(float4*)(As + r * 64 + kk) = v;
        }
        __syncthreads();
        #pragma unroll
        for (int kk = 0; kk < 64; kk += 4) {
            float4 af[8];
            #pragma unroll
            for (int j = 0; j < 8; j++)
                af[j] = *(const float4*)(As + (rbase + j) * 64 + kk);
            #pragma unroll
            for (int q = 0; q < 4; q++) {
                float w1 = Ws1[(k0 + kk + q) * BN + c];
                float w2 = 0.f;
                if constexpr (FUSE2) w2 = Ws2[(k0 + kk + q) * BN + c];
                #pragma unroll
                for (int j = 0; j < 8; j++) {
                    float a = (q == 0) ? af[j].x : (q == 1) ? af[j].y : (q == 2) ? af[j].z : af[j].w;
                    acc1[j] = fmaf(a, w1, acc1[j]);
                    if constexpr (FUSE2) acc2[j] = fmaf(a, w2, acc2[j]);
                }
            }
        }
    }
}

__global__ void __launch_bounds__(NTHR, 1)
recurrent_kernel(const float* __restrict__ inputs,
                 const float* __restrict__ Whp, const float* __restrict__ bhp,
                 const float* __restrict__ Wcp, const float* __restrict__ bcp,
                 const float* __restrict__ Wm,  const float* __restrict__ bm,
                 const float* __restrict__ Whpost, const float* __restrict__ bhpost,
                 const float* __restrict__ Wr1, const float* __restrict__ br1,
                 const float* __restrict__ Wr2, const float* __restrict__ br2,
                 float* __restrict__ out)
{
    extern __shared__ float smem[];
    float* Whp_s    = smem;                   // 256*32
    float* Wm_s     = Whp_s    + 256 * BN;    // 512*32
    float* Whpost_s = Wm_s     + 512 * BN;    // 256*32
    float* Wr1_s    = Whpost_s + 256 * BN;    // 256*32
    float* Wcp_s    = Wr1_s    + 256 * BN;    // 64*32
    float* bias_s   = Wcp_s    + 64 * BN;     // 192 floats
    float* As       = bias_s   + 192;         // 64*64 staging

    const int tid  = threadIdx.x;
    const int bi   = blockIdx.x >> 3;   // batch-row tile 0..15
    const int bj   = blockIdx.x & 7;    // col tile 0..7
    const int row0 = bi * BM;
    const int c0   = bj * BN;
    const int c    = tid & 31;          // lane == output col within tile
    const int rbase = (tid >> 5) * 8;   // 8 rows per thread

    // ---- load resident weight slices ----
    for (int i = tid; i < 256 * BN; i += NTHR) {
        int k = i >> 5, cc = i & 31;
        Whp_s[i]    = Whp[k * RDIM + c0 + cc];
        Whpost_s[i] = Whpost[k * RDIM + c0 + cc];
        Wr1_s[i]    = Wr1[k * RDIM + c0 + cc];
    }
    for (int i = tid; i < 512 * BN; i += NTHR)
        Wm_s[i] = Wm[(i >> 5) * RDIM + c0 + (i & 31)];
    for (int i = tid; i < 64 * BN; i += NTHR)
        Wcp_s[i] = Wcp[(i >> 5) * RDIM + c0 + (i & 31)];
    if (tid < 32) {
        bias_s[tid]       = bhp[c0 + tid];
        bias_s[32 + tid]  = bcp[c0 + tid];
        bias_s[64 + tid]  = bm[c0 + tid];
        bias_s[96 + tid]  = bhpost[c0 + tid];
        bias_s[128 + tid] = br1[c0 + tid];
        bias_s[160 + tid] = Wr2[c0 + tid];   // Wr2 is (256,1)
    }
    const float br2v = __ldg(br2);
    __syncthreads();

    for (int t = 0; t < T_STEPS; t++) {
        // ================= Phase A =================
        // S1: a = tanh(h @ Whp + bhp) -> cat[:, 0:256]
        // S4 (lagged, t>0): r1 = relu(h @ Wr1 + br1); partials of r1 @ Wr2
        if (t > 0) {
            float acc_a[8], acc_r1[8];
            #pragma unroll
            for (int j = 0; j < 8; j++) { acc_a[j] = bias_s[c]; acc_r1[j] = bias_s[128 + c]; }
            gemm64<RDIM, true>(g_h, RDIM, row0, Whp_s, Wr1_s, As, acc_a, acc_r1, c, rbase);
            float w2 = bias_s[160 + c];
            #pragma unroll
            for (int j = 0; j < 8; j++) {
                g_cat[(size_t)(row0 + rbase + j) * (2 * RDIM) + c0 + c] = tanhf(acc_a[j]);
                float v = fmaxf(acc_r1[j], 0.f) * w2;
                #pragma unroll
                for (int off = 16; off > 0; off >>= 1)
                    v += __shfl_down_sync(0xffffffffu, v, off);
                if (c == 0) g_r1p[bj * NBATCH + row0 + rbase + j] = v;
            }
        } else {
            // h0 == 0 -> a = tanh(bhp)
            float av = tanhf(bias_s[c]);
            #pragma unroll
            for (int j = 0; j < 8; j++)
                g_cat[(size_t)(row0 + rbase + j) * (2 * RDIM) + c0 + c] = av;
        }
        // S0: tcp = tanh(x_t @ Wcp + bcp) -> cat[:, 256:512]
        {
            float acc_cp[8];
            #pragma unroll
            for (int j = 0; j < 8; j++) acc_cp[j] = bias_s[32 + c];
            gemm64<IDIM, false>(inputs + (size_t)t * NBATCH * IDIM, IDIM, row0,
                                Wcp_s, (const float*)0, As, acc_cp, acc_cp, c, rbase);
            #pragma unroll
            for (int j = 0; j < 8; j++)
                g_cat[(size_t)(row0 + rbase + j) * (2 * RDIM) + RDIM + c0 + c] = tanhf(acc_cp[j]);
        }
        grid_barrier();

        // ================= Phase B =================
        // S2: m = tanh(cat @ Wm + bm)
        {
            float acc_m[8];
            #pragma unroll
            for (int j = 0; j < 8; j++) acc_m[j] = bias_s[64 + c];
            gemm64<2 * RDIM, false>(g_cat, 2 * RDIM, row0, Wm_s, (const float*)0,
                                    As, acc_m, acc_m, c, rbase);
            #pragma unroll
            for (int j = 0; j < 8; j++)
                g_m[(size_t)(row0 + rbase + j) * RDIM + c0 + c] = tanhf(acc_m[j]);
        }
        // finalize out[t-1]: sum partials across the 8 col-tiles
        if (bj == 0 && t > 0 && tid < BM) {
            int n = row0 + tid;
            float s = br2v;
            #pragma unroll
            for (int jj = 0; jj < 8; jj++)
                s += __ldcg(&g_r1p[jj * NBATCH + n]);
            out[(size_t)(t - 1) * NBATCH + n] = s;
        }
        grid_barrier();

        // ================= Phase C =================
        // S3: h = tanh(m @ Whpost + bhpost)
        {
            float acc_h[8];
            #pragma unroll
            for (int j = 0; j < 8; j++) acc_h[j] = bias_s[96 + c];
            gemm64<RDIM, false>(g_m, RDIM, row0, Whpost_s, (const float*)0,
                                As, acc_h, acc_h, c, rbase);
            #pragma unroll
            for (int j = 0; j < 8; j++)
                g_h[(size_t)(row0 + rbase + j) * RDIM + c0 + c] = tanhf(acc_h[j]);
        }
        grid_barrier();
    }

    // ================= Epilogue: regressor for final step =================
    {
        float acc_r1[8];
        #pragma unroll
        for (int j = 0; j < 8; j++) acc_r1[j] = bias_s[128 + c];
        gemm64<RDIM, false>(g_h, RDIM, row0, Wr1_s, (const float*)0,
                            As, acc_r1, acc_r1, c, rbase);
        float w2 = bias_s[160 + c];
        #pragma unroll
        for (int j = 0; j < 8; j++) {
            float v = fmaxf(acc_r1[j], 0.f) * w2;
            #pragma unroll
            for (int off = 16; off > 0; off >>= 1)
                v += __shfl_down_sync(0xffffffffu, v, off);
            if (c == 0) g_r1p[bj * NBATCH + row0 + rbase + j] = v;
        }
    }
    grid_barrier();
    if (bj == 0 && tid < BM) {
        int n = row0 + tid;
        float s = br2v;
        #pragma unroll
        for (int jj = 0; jj < 8; jj++)
            s += __ldcg(&g_r1p[jj * NBATCH + n]);
        out[(size_t)(T_STEPS - 1) * NBATCH + n] = s;
    }
}

extern "C" void kernel_launch(void* const* d_in, const int* in_sizes, int n_in,
                              void* d_out, int out_size)
{
    (void)in_sizes; (void)n_in; (void)out_size;
    const float* inputs = (const float*)d_in[0];
    const float* Whp    = (const float*)d_in[1];
    const float* bhp    = (const float*)d_in[2];
    const float* Wcp    = (const float*)d_in[3];
    const float* bcp    = (const float*)d_in[4];
    const float* Wm     = (const float*)d_in[5];
    const float* bm     = (const float*)d_in[6];
    const float* Whpost = (const float*)d_in[7];
    const float* bhpost = (const float*)d_in[8];
    const float* Wr1    = (const float*)d_in[9];
    const float* br1    = (const float*)d_in[10];
    const float* Wr2    = (const float*)d_in[11];
    const float* br2    = (const float*)d_in[12];
    float* out = (float*)d_out;

    // dynamic smem: (256+512+256+256+64)*32 + 192 + 64*64 floats = 47296 * 4 B
    const size_t smem_bytes = (size_t)47296 * sizeof(float);
    cudaFuncSetAttribute(recurrent_kernel,
                         cudaFuncAttributeMaxDynamicSharedMemorySize,
                         (int)smem_bytes);

    recurrent_kernel<<<NCTA, NTHR, smem_bytes>>>(
        inputs, Whp, bhp, Wcp, bcp, Wm, bm, Whpost, bhpost,
        Wr1, br1, Wr2, br2, out);
}